// round 12
// baseline (speedup 1.0000x reference)
#include <cuda_runtime.h>
#include <cuda_bf16.h>
#include <cstdint>

#define BB 16
#define TT 64
#define CC 512

// ---------------------------------------------------------------------------
// Device scratch (allocation-free rule)
// ---------------------------------------------------------------------------
__device__ float g_VE[BB * TT * CC];              // x @ W_proj + b_proj (fp32)
__device__ __nv_bfloat16 g_XEh[BB * TT * CC];     // x @ W_x + b_x (bf16)
__device__ __nv_bfloat16 g_WT[3 * CC * CC];       // [Wim^T | Wp^T | Wx^T] bf16 [N][K]

// ---------------------------------------------------------------------------
// Helpers (baseline sm_80+ PTX: mma.sync / ldmatrix / cp.async / tanh.approx)
// ---------------------------------------------------------------------------
__device__ __forceinline__ uint32_t smem_u32(const void* p) {
    uint32_t a;
    asm("{ .reg .u64 t; cvta.to.shared.u64 t, %1; cvt.u32.u64 %0, t; }" : "=r"(a) : "l"(p));
    return a;
}
__device__ __forceinline__ void ldsm4(uint32_t* r, uint32_t addr) {
    asm volatile("ldmatrix.sync.aligned.m8n8.x4.shared.b16 {%0,%1,%2,%3}, [%4];"
        : "=r"(r[0]), "=r"(r[1]), "=r"(r[2]), "=r"(r[3]) : "r"(addr));
}
__device__ __forceinline__ void mma_bf16(float* d, const uint32_t* a, const uint32_t* b) {
    asm volatile("mma.sync.aligned.m16n8k16.row.col.f32.bf16.bf16.f32 "
        "{%0,%1,%2,%3}, {%4,%5,%6,%7}, {%8,%9}, {%0,%1,%2,%3};"
        : "+f"(d[0]), "+f"(d[1]), "+f"(d[2]), "+f"(d[3])
        : "r"(a[0]), "r"(a[1]), "r"(a[2]), "r"(a[3]), "r"(b[0]), "r"(b[1]));
}
__device__ __forceinline__ void cp_async16(uint32_t dst, const void* src) {
    asm volatile("cp.async.cg.shared.global [%0], [%1], 16;" :: "r"(dst), "l"(src));
}
__device__ __forceinline__ float tanh_fast(float v) {
    float y;
    asm("tanh.approx.f32 %0, %1;" : "=f"(y) : "f"(v));
    return y;
}
#define CP_COMMIT()  asm volatile("cp.async.commit_group;" ::: "memory")
#define CP_WAIT0()   asm volatile("cp.async.wait_group 0;" ::: "memory")

// temporal smem byte offsets (total 206848 -> 1 persistent CTA/SM)
#define OFF_F0     0           /* [64]  */
#define OFF_F1     256
#define OFF_MASK   512
#define OFF_SOUT2  768
#define OFF_SEXP   1024        /* [128] */
#define OFF_BIM    1536        /* [512] */
#define OFF_WT0    3584
#define OFF_WT1    5632
#define OFF_BT     7680
#define OFF_A      10240       /* A: [64][512] bf16 swizzled = 65536 B  */
#define OFF_B      75776       /* B: [128][512] bf16 RESIDENT = 131072 */
#define SMEM_BYTES 206848

// embed_mma smem: A [64][512] bf16 = 64 KB, B 2 x 16 KB
#define EMB_OFF_B   65536
#define EMB_SMEM    98304

// ---------------------------------------------------------------------------
// Kernel: zero the out2 region (atomically accumulated by temporal)
// ---------------------------------------------------------------------------
__global__ void zero_out2_kernel(float* __restrict__ out)
{
    out[BB * TT * CC + blockIdx.x * 256 + threadIdx.x] = 0.f;
}

// ---------------------------------------------------------------------------
// Kernel: transpose + cvt all three weight matrices to bf16 [N][K]
// ---------------------------------------------------------------------------
__global__ void prep_w_kernel(const float* __restrict__ Wim,
                              const float* __restrict__ Wp,
                              const float* __restrict__ Wx)
{
    __shared__ float tile[32][33];
    const int z = blockIdx.z;
    const float* src = (z == 0) ? Wim : (z == 1) ? Wp : Wx;
    const int n0 = blockIdx.x * 32, k0 = blockIdx.y * 32;
    tile[threadIdx.y][threadIdx.x] = src[(k0 + threadIdx.y) * CC + n0 + threadIdx.x];
    __syncthreads();
    g_WT[(size_t)(z * CC + n0 + threadIdx.y) * CC + k0 + threadIdx.x] =
        __float2bfloat16(tile[threadIdx.x][threadIdx.y]);
}

// ---------------------------------------------------------------------------
// Kernel: embedding GEMMs on tensor cores.
// [1024, 1024] = x[1024, 512] @ [Wp | Wx][512, 1024]  (bf16, fp32 accum)
// VE half written fp32, XE half written bf16.
// ---------------------------------------------------------------------------
__global__ __launch_bounds__(256, 2) void embed_mma_kernel(
    const float* __restrict__ x,
    const float* __restrict__ bp, const float* __restrict__ bx)
{
    extern __shared__ char sm[];
    const uint32_t smb = smem_u32(sm);
    const int tid = threadIdx.x, lane = tid & 31, wid = tid >> 5;
    const int mt = blockIdx.x & 15, nt = blockIdx.x >> 4;
    const int r0 = mt * 64;

    auto issueB = [&](int s) {
        const int n  = tid >> 1;
        const int cq = (tid & 1) * 4;
        const uint32_t dstRow = smb + EMB_OFF_B + (s & 1) * 16384 + n * 128;
        const __nv_bfloat16* src = g_WT + (size_t)(CC + nt * 128 + n) * CC + s * 64 + cq * 8;
#pragma unroll
        for (int c = 0; c < 4; c++)
            cp_async16(dstRow + (((cq + c) ^ (n & 7)) << 4), src + c * 8);
        CP_COMMIT();
    };
    issueB(0);

    // A = x rows [r0, r0+64) cvt to bf16, swizzled
    {
        const int rbase = wid * 8;
#pragma unroll
        for (int rr = 0; rr < 8; rr++) {
            const int r = rbase + rr;
            const float* xr = x + (size_t)(r0 + r) * CC;
            char* Arow = sm + r * 1024;
            const int xw = r & 7;
#pragma unroll
            for (int pass = 0; pass < 4; pass++) {
                const int k = pass * 128 + lane * 4;
                const float4 xv = *(const float4*)(xr + k);
                uint2 pk;
                ((__nv_bfloat162*)&pk)[0] = __floats2bfloat162_rn(xv.x, xv.y);
                ((__nv_bfloat162*)&pk)[1] = __floats2bfloat162_rn(xv.z, xv.w);
                const int c8 = pass * 16 + (lane >> 1);
                *(uint2*)(Arow + ((c8 ^ xw) << 4) + ((lane & 1) << 3)) = pk;
            }
        }
    }

    const int mw = wid & 1, nw = wid >> 1;
    const int mA  = mw * 32 + (lane & 15);
    const int aC8 = lane >> 4;
    const int aXr = mA & 7;
    const uint32_t aBase = smb + mA * 1024;
    const int nB  = nw * 32 + (lane & 7) + ((lane >> 4) << 3);
    const int bC8 = (lane >> 3) & 1;
    const int bXr = nB & 7;
    const uint32_t bRowOff = (uint32_t)nB * 128;

    float acc[2][4][4];
#pragma unroll
    for (int mf = 0; mf < 2; mf++)
#pragma unroll
        for (int nf = 0; nf < 4; nf++)
#pragma unroll
            for (int d = 0; d < 4; d++) acc[mf][nf][d] = 0.f;

#pragma unroll 1
    for (int s = 0; s < 8; s++) {
        CP_WAIT0();
        __syncthreads();
        if (s < 7) issueB(s + 1);
        const uint32_t Bslot = smb + EMB_OFF_B + (s & 1) * 16384;
#pragma unroll
        for (int t = 0; t < 4; t++) {
            uint32_t a0[4], a1[4], b0[4], b1[4];
            const uint32_t swA = (uint32_t)(((s * 8 + t * 2 + aC8) ^ aXr) << 4);
            ldsm4(a0, aBase + swA);
            ldsm4(a1, aBase + 16384 + swA);
            const uint32_t swB = (uint32_t)(((t * 2 + bC8) ^ bXr) << 4);
            const uint32_t bA = Bslot + bRowOff + swB;
            ldsm4(b0, bA);
            ldsm4(b1, bA + 2048);
            mma_bf16(acc[0][0], a0, b0);
            mma_bf16(acc[0][1], a0, b0 + 2);
            mma_bf16(acc[0][2], a0, b1);
            mma_bf16(acc[0][3], a0, b1 + 2);
            mma_bf16(acc[1][0], a1, b0);
            mma_bf16(acc[1][1], a1, b0 + 2);
            mma_bf16(acc[1][2], a1, b1);
            mma_bf16(acc[1][3], a1, b1 + 2);
        }
    }

    // epilogue: +bias; VE -> fp32, XE -> bf16
    const int qrow = lane >> 2, qcol2 = (lane & 3) * 2;
    const int cbase = (nt & 3) * 128 + nw * 32;
    const float* bias = (nt < 4) ? bp : bx;
    float2 bb[4];
#pragma unroll
    for (int nf = 0; nf < 4; nf++)
        bb[nf] = *(const float2*)(bias + cbase + nf * 8 + qcol2);

    if (nt < 4) {
#pragma unroll
        for (int mf = 0; mf < 2; mf++)
#pragma unroll
            for (int h = 0; h < 2; h++) {
                const int row = r0 + mw * 32 + mf * 16 + h * 8 + qrow;
#pragma unroll
                for (int nf = 0; nf < 4; nf++) {
                    const int col = cbase + nf * 8 + qcol2;
                    *(float2*)(g_VE + (size_t)row * CC + col) =
                        make_float2(acc[mf][nf][h * 2] + bb[nf].x,
                                    acc[mf][nf][h * 2 + 1] + bb[nf].y);
                }
            }
    } else {
#pragma unroll
        for (int mf = 0; mf < 2; mf++)
#pragma unroll
            for (int h = 0; h < 2; h++) {
                const int row = r0 + mw * 32 + mf * 16 + h * 8 + qrow;
#pragma unroll
                for (int nf = 0; nf < 4; nf++) {
                    const int col = cbase + nf * 8 + qcol2;
                    *(__nv_bfloat162*)(g_XEh + (size_t)row * CC + col) =
                        __floats2bfloat162_rn(acc[mf][nf][h * 2] + bb[nf].x,
                                              acc[mf][nf][h * 2 + 1] + bb[nf].y);
                }
            }
    }
}

// ---------------------------------------------------------------------------
// Main kernel: PERSISTENT. 148 CTAs (1/SM), 256 threads = 8 warps.
// CTA owns N-chunk ch = cid&3; B slice [128 n][512 k] resident in smem.
// Loops over (b,i) tiles: A-build -> sync-free 32-iter LDSM/HMMA loop ->
// register epilogue -> out1 direct, out2 via global atomicAdd partials.
// ---------------------------------------------------------------------------
__global__ __launch_bounds__(256, 1) void temporal_kernel(
    const float* __restrict__ x,
    const float* __restrict__ ts,
    const float* __restrict__ amask,
    const float* __restrict__ Wt,  const float* __restrict__ bt,
    const float* __restrict__ bim,
    float* __restrict__ out)
{
    extern __shared__ char sm[];
    const uint32_t smb = smem_u32(sm);
    const int tid  = threadIdx.x;
    const int lane = tid & 31;
    const int wid  = tid >> 5;

    const int chunk = blockIdx.x & 3;
    const int slot  = blockIdx.x >> 2;     // 0..36

    // ---- load resident B slice: [128 n][512 k] bf16, XOR-swizzled ----
    {
        const __nv_bfloat16* Bsrc = g_WT + (size_t)(chunk * 128) * CC;
#pragma unroll 4
        for (int idx = tid; idx < 8192; idx += 256) {
            const int n = idx >> 6, c8 = idx & 63;
            cp_async16(smb + OFF_B + n * 1024 + ((c8 ^ (n & 7)) << 4),
                       Bsrc + (size_t)n * CC + c8 * 8);
        }
        CP_COMMIT();
    }

    float* f0s   = (float*)(sm + OFF_F0);     // [64]
    float* f1s   = (float*)(sm + OFF_F1);
    float* maskv = (float*)(sm + OFF_MASK);
    float* sout2 = (float*)(sm + OFF_SOUT2);  // [64]
    float* sexp  = (float*)(sm + OFF_SEXP);   // [128]
    float* sbim  = (float*)(sm + OFF_BIM);
    float* sWt0  = (float*)(sm + OFF_WT0);
    float* sWt1  = (float*)(sm + OFF_WT1);
    float* sbt   = (float*)(sm + OFF_BT);

    // ---- one-time staging ----
    sbim[tid] = bim[tid];       sbim[tid + 256] = bim[tid + 256];
    sWt0[tid] = Wt[tid];        sWt0[tid + 256] = Wt[tid + 256];
    sWt1[tid] = Wt[CC + tid];   sWt1[tid + 256] = Wt[CC + tid + 256];
    sbt[tid]  = bt[tid];        sbt[tid + 256]  = bt[tid + 256];
    if (tid < 64) sout2[tid] = 0.f;
    if (tid < 128) sexp[tid] = 0.f;

    // ---- warp/lane geometry (warp tile 32m x 32n; 2 mw x 4 nw) ----
    const int mw = wid & 1, nw = wid >> 1;
    const int m0  = mw * 32;
    const int n0w = nw * 32;
    const int mA  = m0 + (lane & 15);
    const int aC8 = lane >> 4;
    const int aXr = mA & 7;
    const uint32_t aBase = smb + OFF_A + mA * 1024;
    const int nB  = n0w + (lane & 7) + ((lane >> 4) << 3);
    const int bC8 = (lane >> 3) & 1;
    const int bXr = nB & 7;
    const uint32_t bBase = smb + OFF_B + (uint32_t)nB * 1024;
    const int qrow = lane >> 2, qcol2 = (lane & 3) * 2;

    float* gout2 = out + BB * TT * CC;

#pragma unroll 1
    for (int t = 0; ; t++) {
        const int idx = slot + 37 * t;
        if (idx >= BB * TT) break;
        const int b = idx >> 6, i = idx & 63;

        // ---- per-tile staging ----
        if (tid < 64) {
            const float rel = ts[b * TT + i] - ts[b * TT + tid];
            f0s[tid] = log1pf(fmaxf(rel, 0.f));
            f1s[tid] = log1pf(fmaxf(-rel, 0.f));
            maskv[tid] = amask[b * TT + tid];
        }
        __syncthreads();   // staging visible; prior tile's epilogue readers done

        // ---- build A = relu(h) [64 j][512 k] bf16, XOR-swizzled ----
        {
            const int rbase = wid * 8;
#pragma unroll
            for (int rr = 0; rr < 8; rr++) {
                const int r = rbase + rr;
                const float f0v = f0s[r], f1v = f1s[r];
                const __nv_bfloat16* XEr = g_XEh + (size_t)(b * TT + r) * CC;
                char* Arow = sm + OFF_A + r * 1024;
                const int xr = r & 7;
#pragma unroll
                for (int pass = 0; pass < 2; pass++) {
                    const int k = pass * 256 + lane * 8;
                    const uint4 xp = *(const uint4*)(XEr + k);
                    const __nv_bfloat162* x2 = (const __nv_bfloat162*)&xp;
                    uint4 pk;
                    __nv_bfloat162* p2 = (__nv_bfloat162*)&pk;
#pragma unroll
                    for (int q = 0; q < 4; q++) {
                        const float2 xe = __bfloat1622float2(x2[q]);
                        const int kk = k + q * 2;
                        const float h0 = fmaxf(fmaf(f0v, sWt0[kk],     fmaf(f1v, sWt1[kk],     sbt[kk]))     + xe.x, 0.f);
                        const float h1 = fmaxf(fmaf(f0v, sWt0[kk + 1], fmaf(f1v, sWt1[kk + 1], sbt[kk + 1])) + xe.y, 0.f);
                        p2[q] = __floats2bfloat162_rn(h0, h1);
                    }
                    const int c8 = pass * 32 + lane;
                    *(uint4*)(Arow + ((c8 ^ xr) << 4)) = pk;
                }
            }
        }
        CP_WAIT0();        // B resident (no-op after first tile)
        __syncthreads();   // A + B ready for all warps

        // ---- MMA mainloop: 32 k-iters, no syncs, no loads from gmem ----
        float acc[2][4][4];
#pragma unroll
        for (int mf = 0; mf < 2; mf++)
#pragma unroll
            for (int nf = 0; nf < 4; nf++)
#pragma unroll
                for (int d = 0; d < 4; d++) acc[mf][nf][d] = 0.f;

#pragma unroll 8
        for (int tk = 0; tk < 32; tk++) {
            uint32_t a0[4], a1[4], b0[4], b1[4];
            const uint32_t swA = (uint32_t)(((tk * 2 + aC8) ^ aXr) << 4);
            ldsm4(a0, aBase + swA);
            ldsm4(a1, aBase + 16384 + swA);
            const uint32_t swB = (uint32_t)(((tk * 2 + bC8) ^ bXr) << 4);
            ldsm4(b0, bBase + swB);
            ldsm4(b1, bBase + 16384 + swB);
            mma_bf16(acc[0][0], a0, b0);
            mma_bf16(acc[0][1], a0, b0 + 2);
            mma_bf16(acc[0][2], a0, b1);
            mma_bf16(acc[0][3], a0, b1 + 2);
            mma_bf16(acc[1][0], a1, b0);
            mma_bf16(acc[1][1], a1, b0 + 2);
            mma_bf16(acc[1][2], a1, b1);
            mma_bf16(acc[1][3], a1, b1 + 2);
        }
        __syncthreads();   // MMAs done -> A free for next tile

        // ---- register epilogue: sigmoid via tanh.approx, fused reductions ----
        float bimv[8], cs[8];
#pragma unroll
        for (int nf = 0; nf < 4; nf++) {
            bimv[nf * 2]     = sbim[chunk * 128 + n0w + nf * 8 + qcol2];
            bimv[nf * 2 + 1] = sbim[chunk * 128 + n0w + nf * 8 + qcol2 + 1];
            cs[nf * 2] = 0.f; cs[nf * 2 + 1] = 0.f;
        }
        float rs[4];
#pragma unroll
        for (int mf = 0; mf < 2; mf++) {
#pragma unroll
            for (int h = 0; h < 2; h++) {
                const int r  = m0 + mf * 16 + h * 8 + qrow;
                const float hmk = 0.5f * maskv[r];
                const float* VEr = g_VE + (size_t)(b * TT + r) * CC
                                   + chunk * 128 + n0w + qcol2;
                float rsum = 0.f;
#pragma unroll
                for (int nf = 0; nf < 4; nf++) {
                    const float2 ve = *(const float2*)(VEr + nf * 8);
                    const float s0 = acc[mf][nf][h * 2 + 0] + bimv[nf * 2];
                    const float s1 = acc[mf][nf][h * 2 + 1] + bimv[nf * 2 + 1];
                    const float p0 = fmaf(tanh_fast(0.5f * s0), hmk, hmk);
                    const float p1 = fmaf(tanh_fast(0.5f * s1), hmk, hmk);
                    rsum += p0 + p1;
                    cs[nf * 2]     += __expf(ve.x * p0);
                    cs[nf * 2 + 1] += __expf(ve.y * p1);
                }
                rs[mf * 2 + h] = rsum;
            }
        }
        // row sums -> sout2 (reduce over the 4 qcol lanes)
#pragma unroll
        for (int q = 0; q < 4; q++) {
            rs[q] += __shfl_xor_sync(0xffffffffu, rs[q], 1);
            rs[q] += __shfl_xor_sync(0xffffffffu, rs[q], 2);
        }
        if ((lane & 3) == 0) {
#pragma unroll
            for (int q = 0; q < 4; q++)
                atomicAdd(&sout2[m0 + (q >> 1) * 16 + (q & 1) * 8 + qrow], rs[q]);
        }
        // column exp-sums -> sexp (reduce over the 8 qrow lanes)
#pragma unroll
        for (int c = 0; c < 8; c++) {
            cs[c] += __shfl_xor_sync(0xffffffffu, cs[c], 4);
            cs[c] += __shfl_xor_sync(0xffffffffu, cs[c], 8);
            cs[c] += __shfl_xor_sync(0xffffffffu, cs[c], 16);
        }
        if (lane < 4) {
#pragma unroll
            for (int nf = 0; nf < 4; nf++) {
                atomicAdd(&sexp[n0w + nf * 8 + lane * 2],     cs[nf * 2]);
                atomicAdd(&sexp[n0w + nf * 8 + lane * 2 + 1], cs[nf * 2 + 1]);
            }
        }
        __syncthreads();

        // ---- outputs ----
        if (tid < 128) {
            const int ng = chunk * 128 + tid;
            const int row = b * TT + i;
            out[(size_t)row * CC + ng] = x[(size_t)row * CC + ng] + __logf(sexp[tid]);
            sexp[tid] = 0.f;
        }
        if (tid < 64) {
            atomicAdd(&gout2[(b * TT + i) * TT + tid], sout2[tid] * (1.f / 512.f));
            sout2[tid] = 0.f;
        }
        // next iteration's first sync orders these resets against reuse
    }
}

// ---------------------------------------------------------------------------
extern "C" void kernel_launch(void* const* d_in, const int* in_sizes, int n_in,
                              void* d_out, int out_size)
{
    const float* x     = (const float*)d_in[0];
    const float* ts    = (const float*)d_in[1];
    const float* amask = (const float*)d_in[2];
    const float* Wp    = (const float*)d_in[3];
    const float* bp    = (const float*)d_in[4];
    const float* Wx    = (const float*)d_in[5];
    const float* bx    = (const float*)d_in[6];
    const float* Wt    = (const float*)d_in[7];
    const float* bt    = (const float*)d_in[8];
    const float* Wim   = (const float*)d_in[9];
    const float* bim   = (const float*)d_in[10];
    float* out = (float*)d_out;

    zero_out2_kernel<<<256, 256>>>(out);
    prep_w_kernel<<<dim3(16, 16, 3), dim3(32, 32)>>>(Wim, Wp, Wx);

    cudaFuncSetAttribute(embed_mma_kernel, cudaFuncAttributeMaxDynamicSharedMemorySize, EMB_SMEM);
    embed_mma_kernel<<<128, 256, EMB_SMEM>>>(x, bp, bx);

    cudaFuncSetAttribute(temporal_kernel, cudaFuncAttributeMaxDynamicSharedMemorySize, SMEM_BYTES);
    temporal_kernel<<<148, 256, SMEM_BYTES>>>(x, ts, amask, Wt, bt, bim, out);
}

// round 13
// speedup vs baseline: 1.2090x; 1.2090x over previous
#include <cuda_runtime.h>
#include <cuda_bf16.h>
#include <cstdint>

#define BB 16
#define TT 64
#define CC 512

// ---------------------------------------------------------------------------
// Device scratch (allocation-free rule)
// ---------------------------------------------------------------------------
__device__ float g_VE[BB * TT * CC];              // x @ W_proj + b_proj (fp32)
__device__ __nv_bfloat16 g_XEh[BB * TT * CC];     // x @ W_x + b_x (bf16)
__device__ __nv_bfloat16 g_WT[3 * CC * CC];       // [Wim^T | Wp^T | Wx^T] bf16 [N][K]

// ---------------------------------------------------------------------------
// Helpers (baseline sm_80+ PTX: mma.sync / ldmatrix / cp.async / tanh.approx)
// ---------------------------------------------------------------------------
__device__ __forceinline__ uint32_t smem_u32(const void* p) {
    uint32_t a;
    asm("{ .reg .u64 t; cvta.to.shared.u64 t, %1; cvt.u32.u64 %0, t; }" : "=r"(a) : "l"(p));
    return a;
}
__device__ __forceinline__ void ldsm4(uint32_t* r, uint32_t addr) {
    asm volatile("ldmatrix.sync.aligned.m8n8.x4.shared.b16 {%0,%1,%2,%3}, [%4];"
        : "=r"(r[0]), "=r"(r[1]), "=r"(r[2]), "=r"(r[3]) : "r"(addr));
}
__device__ __forceinline__ void mma_bf16(float* d, const uint32_t* a, const uint32_t* b) {
    asm volatile("mma.sync.aligned.m16n8k16.row.col.f32.bf16.bf16.f32 "
        "{%0,%1,%2,%3}, {%4,%5,%6,%7}, {%8,%9}, {%0,%1,%2,%3};"
        : "+f"(d[0]), "+f"(d[1]), "+f"(d[2]), "+f"(d[3])
        : "r"(a[0]), "r"(a[1]), "r"(a[2]), "r"(a[3]), "r"(b[0]), "r"(b[1]));
}
__device__ __forceinline__ void cp_async16(uint32_t dst, const void* src) {
    asm volatile("cp.async.cg.shared.global [%0], [%1], 16;" :: "r"(dst), "l"(src));
}
__device__ __forceinline__ float tanh_fast(float v) {
    float y;
    asm("tanh.approx.f32 %0, %1;" : "=f"(y) : "f"(v));
    return y;
}
__device__ __forceinline__ void bar_grp(int id) {
    asm volatile("bar.sync %0, 128;" :: "r"(id) : "memory");
}
#define CP_COMMIT()  asm volatile("cp.async.commit_group;" ::: "memory")
#define CP_WAIT0()   asm volatile("cp.async.wait_group 0;" ::: "memory")

// temporal smem layout (212992 B total, 1 persistent CTA/SM)
#define OFF_WT0    0           /* [512] f32 */
#define OFF_WT1    2048
#define OFF_BT     4096
#define OFF_BIM    6144
#define OFF_GRP    8192        /* per-group 1536 B: f0[64],f1[64],mask[64],sout2[64],sexp[128] */
#define GRP_F0     0
#define GRP_F1     256
#define GRP_MASK   512
#define GRP_SOUT2  768
#define GRP_SEXP   1024
#define OFF_A      16384       /* 4 groups x [64 rows][128 k] bf16 = 4 x 16384 */
#define OFF_B      81920       /* [128 n][512 k] bf16 resident = 131072 */
#define SMEM_BYTES 212992

// embed_mma smem: A [64][512] bf16 = 64 KB, B 2 x 16 KB
#define EMB_OFF_B   65536
#define EMB_SMEM    98304

// ---------------------------------------------------------------------------
__global__ void zero_out2_kernel(float* __restrict__ out)
{
    out[BB * TT * CC + blockIdx.x * 256 + threadIdx.x] = 0.f;
}

// ---------------------------------------------------------------------------
// Kernel: transpose + cvt all three weight matrices to bf16 [N][K]
// ---------------------------------------------------------------------------
__global__ void prep_w_kernel(const float* __restrict__ Wim,
                              const float* __restrict__ Wp,
                              const float* __restrict__ Wx)
{
    __shared__ float tile[32][33];
    const int z = blockIdx.z;
    const float* src = (z == 0) ? Wim : (z == 1) ? Wp : Wx;
    const int n0 = blockIdx.x * 32, k0 = blockIdx.y * 32;
    tile[threadIdx.y][threadIdx.x] = src[(k0 + threadIdx.y) * CC + n0 + threadIdx.x];
    __syncthreads();
    g_WT[(size_t)(z * CC + n0 + threadIdx.y) * CC + k0 + threadIdx.x] =
        __float2bfloat16(tile[threadIdx.x][threadIdx.y]);
}

// ---------------------------------------------------------------------------
// Kernel: embedding GEMMs on tensor cores (unchanged from R12).
// ---------------------------------------------------------------------------
__global__ __launch_bounds__(256, 2) void embed_mma_kernel(
    const float* __restrict__ x,
    const float* __restrict__ bp, const float* __restrict__ bx)
{
    extern __shared__ char sm[];
    const uint32_t smb = smem_u32(sm);
    const int tid = threadIdx.x, lane = tid & 31, wid = tid >> 5;
    const int mt = blockIdx.x & 15, nt = blockIdx.x >> 4;
    const int r0 = mt * 64;

    auto issueB = [&](int s) {
        const int n  = tid >> 1;
        const int cq = (tid & 1) * 4;
        const uint32_t dstRow = smb + EMB_OFF_B + (s & 1) * 16384 + n * 128;
        const __nv_bfloat16* src = g_WT + (size_t)(CC + nt * 128 + n) * CC + s * 64 + cq * 8;
#pragma unroll
        for (int c = 0; c < 4; c++)
            cp_async16(dstRow + (((cq + c) ^ (n & 7)) << 4), src + c * 8);
        CP_COMMIT();
    };
    issueB(0);

    {
        const int rbase = wid * 8;
#pragma unroll
        for (int rr = 0; rr < 8; rr++) {
            const int r = rbase + rr;
            const float* xr = x + (size_t)(r0 + r) * CC;
            char* Arow = sm + r * 1024;
            const int xw = r & 7;
#pragma unroll
            for (int pass = 0; pass < 4; pass++) {
                const int k = pass * 128 + lane * 4;
                const float4 xv = *(const float4*)(xr + k);
                uint2 pk;
                ((__nv_bfloat162*)&pk)[0] = __floats2bfloat162_rn(xv.x, xv.y);
                ((__nv_bfloat162*)&pk)[1] = __floats2bfloat162_rn(xv.z, xv.w);
                const int c8 = pass * 16 + (lane >> 1);
                *(uint2*)(Arow + ((c8 ^ xw) << 4) + ((lane & 1) << 3)) = pk;
            }
        }
    }

    const int mw = wid & 1, nw = wid >> 1;
    const int mA  = mw * 32 + (lane & 15);
    const int aC8 = lane >> 4;
    const int aXr = mA & 7;
    const uint32_t aBase = smb + mA * 1024;
    const int nB  = nw * 32 + (lane & 7) + ((lane >> 4) << 3);
    const int bC8 = (lane >> 3) & 1;
    const int bXr = nB & 7;
    const uint32_t bRowOff = (uint32_t)nB * 128;

    float acc[2][4][4];
#pragma unroll
    for (int mf = 0; mf < 2; mf++)
#pragma unroll
        for (int nf = 0; nf < 4; nf++)
#pragma unroll
            for (int d = 0; d < 4; d++) acc[mf][nf][d] = 0.f;

#pragma unroll 1
    for (int s = 0; s < 8; s++) {
        CP_WAIT0();
        __syncthreads();
        if (s < 7) issueB(s + 1);
        const uint32_t Bslot = smb + EMB_OFF_B + (s & 1) * 16384;
#pragma unroll
        for (int t = 0; t < 4; t++) {
            uint32_t a0[4], a1[4], b0[4], b1[4];
            const uint32_t swA = (uint32_t)(((s * 8 + t * 2 + aC8) ^ aXr) << 4);
            ldsm4(a0, aBase + swA);
            ldsm4(a1, aBase + 16384 + swA);
            const uint32_t swB = (uint32_t)(((t * 2 + bC8) ^ bXr) << 4);
            const uint32_t bA = Bslot + bRowOff + swB;
            ldsm4(b0, bA);
            ldsm4(b1, bA + 2048);
            mma_bf16(acc[0][0], a0, b0);
            mma_bf16(acc[0][1], a0, b0 + 2);
            mma_bf16(acc[0][2], a0, b1);
            mma_bf16(acc[0][3], a0, b1 + 2);
            mma_bf16(acc[1][0], a1, b0);
            mma_bf16(acc[1][1], a1, b0 + 2);
            mma_bf16(acc[1][2], a1, b1);
            mma_bf16(acc[1][3], a1, b1 + 2);
        }
    }

    const int qrow = lane >> 2, qcol2 = (lane & 3) * 2;
    const int cbase = (nt & 3) * 128 + nw * 32;
    const float* bias = (nt < 4) ? bp : bx;
    float2 bb[4];
#pragma unroll
    for (int nf = 0; nf < 4; nf++)
        bb[nf] = *(const float2*)(bias + cbase + nf * 8 + qcol2);

    if (nt < 4) {
#pragma unroll
        for (int mf = 0; mf < 2; mf++)
#pragma unroll
            for (int h = 0; h < 2; h++) {
                const int row = r0 + mw * 32 + mf * 16 + h * 8 + qrow;
#pragma unroll
                for (int nf = 0; nf < 4; nf++) {
                    const int col = cbase + nf * 8 + qcol2;
                    *(float2*)(g_VE + (size_t)row * CC + col) =
                        make_float2(acc[mf][nf][h * 2] + bb[nf].x,
                                    acc[mf][nf][h * 2 + 1] + bb[nf].y);
                }
            }
    } else {
#pragma unroll
        for (int mf = 0; mf < 2; mf++)
#pragma unroll
            for (int h = 0; h < 2; h++) {
                const int row = r0 + mw * 32 + mf * 16 + h * 8 + qrow;
#pragma unroll
                for (int nf = 0; nf < 4; nf++) {
                    const int col = cbase + nf * 8 + qcol2;
                    *(__nv_bfloat162*)(g_XEh + (size_t)row * CC + col) =
                        __floats2bfloat162_rn(acc[mf][nf][h * 2] + bb[nf].x,
                                              acc[mf][nf][h * 2 + 1] + bb[nf].y);
                }
            }
    }
}

// ---------------------------------------------------------------------------
// Main kernel: PERSISTENT, 148 CTAs x 512 threads. CTA owns N-chunk
// (B[128][512] resident). 4 INDEPENDENT warpgroups of 4 warps, each with a
// private A-quarter buffer and its own (b,i)-tile stream; group-local named
// barriers so groups' A-build/MMA/epilogue phases overlap on the SM.
// Warp tile 32m x 64n. K processed in 4 quarters of 128.
// ---------------------------------------------------------------------------
__global__ __launch_bounds__(512, 1) void temporal_kernel(
    const float* __restrict__ x,
    const float* __restrict__ ts,
    const float* __restrict__ amask,
    const float* __restrict__ Wt,  const float* __restrict__ bt,
    const float* __restrict__ bim,
    float* __restrict__ out)
{
    extern __shared__ char sm[];
    const uint32_t smb = smem_u32(sm);
    const int tid   = threadIdx.x;
    const int lane  = tid & 31;
    const int g     = tid >> 7;          // warpgroup 0..3
    const int wg    = (tid >> 5) & 3;    // warp within group
    const int tid_g = tid & 127;

    const int chunk = blockIdx.x & 3;
    const int slot  = blockIdx.x >> 2;   // 0..36
    const int stream = slot * 4 + g;     // 0..147 within this chunk

    // ---- load resident B slice [128 n][512 k], XOR-swizzled (all 512 thr) ----
    {
        const __nv_bfloat16* Bsrc = g_WT + (size_t)(chunk * 128) * CC;
#pragma unroll 4
        for (int idx = tid; idx < 8192; idx += 512) {
            const int n = idx >> 6, c8 = idx & 63;
            cp_async16(smb + OFF_B + n * 1024 + ((c8 ^ (n & 7)) << 4),
                       Bsrc + (size_t)n * CC + c8 * 8);
        }
        CP_COMMIT();
    }

    float* sWt0 = (float*)(sm + OFF_WT0);
    float* sWt1 = (float*)(sm + OFF_WT1);
    float* sbt  = (float*)(sm + OFF_BT);
    float* sbim = (float*)(sm + OFF_BIM);
    char*  grp  = sm + OFF_GRP + g * 1536;
    float* f0s   = (float*)(grp + GRP_F0);
    float* f1s   = (float*)(grp + GRP_F1);
    float* maskv = (float*)(grp + GRP_MASK);
    float* sout2 = (float*)(grp + GRP_SOUT2);
    float* sexp  = (float*)(grp + GRP_SEXP);

    sWt0[tid] = Wt[tid];
    sWt1[tid] = Wt[CC + tid];
    sbt[tid]  = bt[tid];
    sbim[tid] = bim[tid];
    if (tid_g < 128) sexp[tid_g] = 0.f;
    if (tid_g < 64)  sout2[tid_g] = 0.f;

    CP_WAIT0();
    __syncthreads();   // B + staging visible to everyone; groups diverge after

    // ---- geometry: 4 warps/group, warp tile 32m x 64n over M=64, N=128 ----
    const int mw = wg & 1, nw = wg >> 1;
    const int m0  = mw * 32;
    const int n0w = nw * 64;
    const int mA  = m0 + (lane & 15);
    const int aC8 = lane >> 4;
    const int aXr = mA & 7;
    const uint32_t aBase = smb + OFF_A + g * 16384 + (uint32_t)mA * 256;
    const int nB  = n0w + (lane & 7) + ((lane >> 4) << 3);
    const int bC8 = (lane >> 3) & 1;
    const int bXr = nB & 7;
    const uint32_t bBase = smb + OFF_B + (uint32_t)nB * 1024;
    const int qrow = lane >> 2, qcol2 = (lane & 3) * 2;
    char* Ag = sm + OFF_A + g * 16384;

    float* gout2 = out + BB * TT * CC;
    const int ntiles = (stream < 136) ? 7 : 6;   // 1024 = 148*6 + 136

#pragma unroll 1
    for (int t = 0; t < ntiles; t++) {
        const int idx = stream + 148 * t;
        const int b = idx >> 6, i = idx & 63;

        // ---- per-tile staging (group-local) ----
        if (tid_g < 64) {
            const float rel = ts[b * TT + i] - ts[b * TT + tid_g];
            f0s[tid_g] = log1pf(fmaxf(rel, 0.f));
            f1s[tid_g] = log1pf(fmaxf(-rel, 0.f));
            maskv[tid_g] = amask[b * TT + tid_g];
        }
        bar_grp(g + 1);

        float acc[2][8][4];
#pragma unroll
        for (int mf = 0; mf < 2; mf++)
#pragma unroll
            for (int nf = 0; nf < 8; nf++)
#pragma unroll
                for (int d = 0; d < 4; d++) acc[mf][nf][d] = 0.f;

        // ---- K quarters: build private A[64][128] then 8 k16 MMA iters ----
#pragma unroll 1
        for (int q = 0; q < 4; q++) {
            // A-build: 4 warps x 16 rows; lanes 0-15 row r, 16-31 row r+1
            {
                const int rowbase = wg * 16 + (lane >> 4);
                const int c = lane & 15;
                const int kk = q * 128 + c * 8;
                const float4 w0a = *(const float4*)(sWt0 + kk);
                const float4 w0b = *(const float4*)(sWt0 + kk + 4);
                const float4 w1a = *(const float4*)(sWt1 + kk);
                const float4 w1b = *(const float4*)(sWt1 + kk + 4);
                const float4 bta = *(const float4*)(sbt + kk);
                const float4 btb = *(const float4*)(sbt + kk + 4);
#pragma unroll
                for (int it = 0; it < 8; it++) {
                    const int r = rowbase + it * 2;
                    const float f0v = f0s[r], f1v = f1s[r];
                    const uint4 xp = *(const uint4*)(g_XEh + (size_t)(b * TT + r) * CC + kk);
                    const __nv_bfloat162* x2 = (const __nv_bfloat162*)&xp;
                    uint4 pk;
                    __nv_bfloat162* p2 = (__nv_bfloat162*)&pk;
                    float2 xe;
                    xe = __bfloat1622float2(x2[0]);
                    p2[0] = __floats2bfloat162_rn(
                        fmaxf(fmaf(f0v, w0a.x, fmaf(f1v, w1a.x, bta.x)) + xe.x, 0.f),
                        fmaxf(fmaf(f0v, w0a.y, fmaf(f1v, w1a.y, bta.y)) + xe.y, 0.f));
                    xe = __bfloat1622float2(x2[1]);
                    p2[1] = __floats2bfloat162_rn(
                        fmaxf(fmaf(f0v, w0a.z, fmaf(f1v, w1a.z, bta.z)) + xe.x, 0.f),
                        fmaxf(fmaf(f0v, w0a.w, fmaf(f1v, w1a.w, bta.w)) + xe.y, 0.f));
                    xe = __bfloat1622float2(x2[2]);
                    p2[2] = __floats2bfloat162_rn(
                        fmaxf(fmaf(f0v, w0b.x, fmaf(f1v, w1b.x, btb.x)) + xe.x, 0.f),
                        fmaxf(fmaf(f0v, w0b.y, fmaf(f1v, w1b.y, btb.y)) + xe.y, 0.f));
                    xe = __bfloat1622float2(x2[3]);
                    p2[3] = __floats2bfloat162_rn(
                        fmaxf(fmaf(f0v, w0b.z, fmaf(f1v, w1b.z, btb.z)) + xe.x, 0.f),
                        fmaxf(fmaf(f0v, w0b.w, fmaf(f1v, w1b.w, btb.w)) + xe.y, 0.f));
                    *(uint4*)(Ag + r * 256 + ((c ^ (r & 7)) << 4)) = pk;
                }
            }
            bar_grp(g + 1);   // A quarter ready

            // MMA: 8 k16 iterations against resident B
#pragma unroll
            for (int tk = 0; tk < 8; tk++) {
                uint32_t a0[4], a1[4], bf[4][4];
                const uint32_t swA = (uint32_t)(((tk * 2 + aC8) ^ aXr) << 4);
                ldsm4(a0, aBase + swA);
                ldsm4(a1, aBase + 4096 + swA);     // +16 rows * 256 B
                const uint32_t cB = (uint32_t)(q * 16 + tk * 2 + bC8);
                const uint32_t swB = ((cB ^ bXr) << 4);
                ldsm4(bf[0], bBase + swB);
                ldsm4(bf[1], bBase + 16384 + swB); // +16 n rows * 1024 B
                ldsm4(bf[2], bBase + 32768 + swB);
                ldsm4(bf[3], bBase + 49152 + swB);
#pragma unroll
                for (int qq = 0; qq < 4; qq++) {
                    mma_bf16(acc[0][qq * 2],     a0, bf[qq]);
                    mma_bf16(acc[0][qq * 2 + 1], a0, bf[qq] + 2);
                    mma_bf16(acc[1][qq * 2],     a1, bf[qq]);
                    mma_bf16(acc[1][qq * 2 + 1], a1, bf[qq] + 2);
                }
            }
            bar_grp(g + 1);   // MMAs done before next quarter's A overwrite
        }

        // ---- register epilogue (two n-halves), group-local reductions ----
        float rs[4] = {0.f, 0.f, 0.f, 0.f};
#pragma unroll
        for (int nh = 0; nh < 2; nh++) {
            float bimv[8], cs[8];
#pragma unroll
            for (int nf = 0; nf < 4; nf++) {
                bimv[nf * 2]     = sbim[chunk * 128 + n0w + nh * 32 + nf * 8 + qcol2];
                bimv[nf * 2 + 1] = sbim[chunk * 128 + n0w + nh * 32 + nf * 8 + qcol2 + 1];
                cs[nf * 2] = 0.f; cs[nf * 2 + 1] = 0.f;
            }
#pragma unroll
            for (int mf = 0; mf < 2; mf++) {
#pragma unroll
                for (int h = 0; h < 2; h++) {
                    const int r  = m0 + mf * 16 + h * 8 + qrow;
                    const float hmk = 0.5f * maskv[r];
                    const float* VEr = g_VE + (size_t)(b * TT + r) * CC
                                       + chunk * 128 + n0w + nh * 32 + qcol2;
                    float rsum = 0.f;
#pragma unroll
                    for (int nf = 0; nf < 4; nf++) {
                        const float2 ve = *(const float2*)(VEr + nf * 8);
                        const float s0 = acc[mf][nh * 4 + nf][h * 2 + 0] + bimv[nf * 2];
                        const float s1 = acc[mf][nh * 4 + nf][h * 2 + 1] + bimv[nf * 2 + 1];
                        const float p0 = fmaf(tanh_fast(0.5f * s0), hmk, hmk);
                        const float p1 = fmaf(tanh_fast(0.5f * s1), hmk, hmk);
                        rsum += p0 + p1;
                        cs[nf * 2]     += __expf(ve.x * p0);
                        cs[nf * 2 + 1] += __expf(ve.y * p1);
                    }
                    rs[mf * 2 + h] += rsum;
                }
            }
#pragma unroll
            for (int c = 0; c < 8; c++) {
                cs[c] += __shfl_xor_sync(0xffffffffu, cs[c], 4);
                cs[c] += __shfl_xor_sync(0xffffffffu, cs[c], 8);
                cs[c] += __shfl_xor_sync(0xffffffffu, cs[c], 16);
            }
            if (lane < 4) {
#pragma unroll
                for (int nf = 0; nf < 4; nf++) {
                    atomicAdd(&sexp[n0w + nh * 32 + nf * 8 + lane * 2],     cs[nf * 2]);
                    atomicAdd(&sexp[n0w + nh * 32 + nf * 8 + lane * 2 + 1], cs[nf * 2 + 1]);
                }
            }
        }
#pragma unroll
        for (int q = 0; q < 4; q++) {
            rs[q] += __shfl_xor_sync(0xffffffffu, rs[q], 1);
            rs[q] += __shfl_xor_sync(0xffffffffu, rs[q], 2);
        }
        if ((lane & 3) == 0) {
#pragma unroll
            for (int q = 0; q < 4; q++)
                atomicAdd(&sout2[m0 + (q >> 1) * 16 + (q & 1) * 8 + qrow], rs[q]);
        }
        bar_grp(g + 1);

        // ---- outputs ----
        if (tid_g < 128) {
            const int ng = chunk * 128 + tid_g;
            const int row = b * TT + i;
            out[(size_t)row * CC + ng] = x[(size_t)row * CC + ng] + __logf(sexp[tid_g]);
            sexp[tid_g] = 0.f;
        }
        if (tid_g < 64) {
            atomicAdd(&gout2[(b * TT + i) * TT + tid_g], sout2[tid_g] * (1.f / 512.f));
            sout2[tid_g] = 0.f;
        }
        bar_grp(g + 1);   // resets + maskv reads done before next tile's staging
    }
}

// ---------------------------------------------------------------------------
extern "C" void kernel_launch(void* const* d_in, const int* in_sizes, int n_in,
                              void* d_out, int out_size)
{
    const float* x     = (const float*)d_in[0];
    const float* ts    = (const float*)d_in[1];
    const float* amask = (const float*)d_in[2];
    const float* Wp    = (const float*)d_in[3];
    const float* bp    = (const float*)d_in[4];
    const float* Wx    = (const float*)d_in[5];
    const float* bx    = (const float*)d_in[6];
    const float* Wt    = (const float*)d_in[7];
    const float* bt    = (const float*)d_in[8];
    const float* Wim   = (const float*)d_in[9];
    const float* bim   = (const float*)d_in[10];
    float* out = (float*)d_out;

    zero_out2_kernel<<<256, 256>>>(out);
    prep_w_kernel<<<dim3(16, 16, 3), dim3(32, 32)>>>(Wim, Wp, Wx);

    cudaFuncSetAttribute(embed_mma_kernel, cudaFuncAttributeMaxDynamicSharedMemorySize, EMB_SMEM);
    embed_mma_kernel<<<128, 256, EMB_SMEM>>>(x, bp, bx);

    cudaFuncSetAttribute(temporal_kernel, cudaFuncAttributeMaxDynamicSharedMemorySize, SMEM_BYTES);
    temporal_kernel<<<148, 512, SMEM_BYTES>>>(x, ts, amask, Wt, bt, bim, out);
}

// round 14
// speedup vs baseline: 1.3471x; 1.1142x over previous
#include <cuda_runtime.h>
#include <cuda_bf16.h>
#include <cstdint>

#define BB 16
#define TT 64
#define CC 512

// ---------------------------------------------------------------------------
// Device scratch (allocation-free rule)
// ---------------------------------------------------------------------------
__device__ float g_VE[BB * TT * CC];              // x @ W_proj + b_proj (fp32)
__device__ __nv_bfloat16 g_XEh[BB * TT * CC];     // x @ W_x + b_x (bf16)
__device__ __nv_bfloat16 g_WT[3 * CC * CC];       // [Wim^T | Wp^T | Wx^T] bf16 [N][K]

// ---------------------------------------------------------------------------
// Helpers (baseline sm_80+ PTX: mma.sync / ldmatrix / cp.async / tanh.approx)
// ---------------------------------------------------------------------------
__device__ __forceinline__ uint32_t smem_u32(const void* p) {
    uint32_t a;
    asm("{ .reg .u64 t; cvta.to.shared.u64 t, %1; cvt.u32.u64 %0, t; }" : "=r"(a) : "l"(p));
    return a;
}
__device__ __forceinline__ void ldsm4(uint32_t* r, uint32_t addr) {
    asm volatile("ldmatrix.sync.aligned.m8n8.x4.shared.b16 {%0,%1,%2,%3}, [%4];"
        : "=r"(r[0]), "=r"(r[1]), "=r"(r[2]), "=r"(r[3]) : "r"(addr));
}
__device__ __forceinline__ void mma_bf16(float* d, const uint32_t* a, const uint32_t* b) {
    asm volatile("mma.sync.aligned.m16n8k16.row.col.f32.bf16.bf16.f32 "
        "{%0,%1,%2,%3}, {%4,%5,%6,%7}, {%8,%9}, {%0,%1,%2,%3};"
        : "+f"(d[0]), "+f"(d[1]), "+f"(d[2]), "+f"(d[3])
        : "r"(a[0]), "r"(a[1]), "r"(a[2]), "r"(a[3]), "r"(b[0]), "r"(b[1]));
}
__device__ __forceinline__ void cp_async16(uint32_t dst, const void* src) {
    asm volatile("cp.async.cg.shared.global [%0], [%1], 16;" :: "r"(dst), "l"(src));
}
__device__ __forceinline__ float tanh_fast(float v) {
    float y;
    asm("tanh.approx.f32 %0, %1;" : "=f"(y) : "f"(v));
    return y;
}
__device__ __forceinline__ void bar_grp(int id) {
    asm volatile("bar.sync %0, 128;" :: "r"(id) : "memory");
}
#define CP_COMMIT()  asm volatile("cp.async.commit_group;" ::: "memory")
#define CP_WAIT0()   asm volatile("cp.async.wait_group 0;" ::: "memory")

// temporal smem layout (212992 B total, 1 persistent CTA/SM)
#define OFF_WT0    0           /* [512] f32 */
#define OFF_WT1    2048
#define OFF_BT     4096
#define OFF_BIM    6144
#define OFF_GRP    8192        /* per-group 1536 B */
#define GRP_F0     0
#define GRP_F1     256
#define GRP_MASK   512
#define GRP_SOUT2  768
#define GRP_SEXP   1024
#define OFF_A      16384       /* 4 groups x 2 slots x [64 rows][64 k] bf16 (8192 B each) */
#define OFF_B      81920       /* [128 n][512 k] bf16 resident = 131072 */
#define SMEM_BYTES 212992

// embed_mma smem: A [64][512] bf16 = 64 KB, B 2 x 16 KB
#define EMB_OFF_B   65536
#define EMB_SMEM    98304

// ---------------------------------------------------------------------------
__global__ void zero_out2_kernel(float* __restrict__ out)
{
    out[BB * TT * CC + blockIdx.x * 256 + threadIdx.x] = 0.f;
}

// ---------------------------------------------------------------------------
// Kernel: transpose + cvt all three weight matrices to bf16 [N][K]
// ---------------------------------------------------------------------------
__global__ void prep_w_kernel(const float* __restrict__ Wim,
                              const float* __restrict__ Wp,
                              const float* __restrict__ Wx)
{
    __shared__ float tile[32][33];
    const int z = blockIdx.z;
    const float* src = (z == 0) ? Wim : (z == 1) ? Wp : Wx;
    const int n0 = blockIdx.x * 32, k0 = blockIdx.y * 32;
    tile[threadIdx.y][threadIdx.x] = src[(k0 + threadIdx.y) * CC + n0 + threadIdx.x];
    __syncthreads();
    g_WT[(size_t)(z * CC + n0 + threadIdx.y) * CC + k0 + threadIdx.x] =
        __float2bfloat16(tile[threadIdx.x][threadIdx.y]);
}

// ---------------------------------------------------------------------------
// Kernel: embedding GEMMs on tensor cores (unchanged).
// ---------------------------------------------------------------------------
__global__ __launch_bounds__(256, 2) void embed_mma_kernel(
    const float* __restrict__ x,
    const float* __restrict__ bp, const float* __restrict__ bx)
{
    extern __shared__ char sm[];
    const uint32_t smb = smem_u32(sm);
    const int tid = threadIdx.x, lane = tid & 31, wid = tid >> 5;
    const int mt = blockIdx.x & 15, nt = blockIdx.x >> 4;
    const int r0 = mt * 64;

    auto issueB = [&](int s) {
        const int n  = tid >> 1;
        const int cq = (tid & 1) * 4;
        const uint32_t dstRow = smb + EMB_OFF_B + (s & 1) * 16384 + n * 128;
        const __nv_bfloat16* src = g_WT + (size_t)(CC + nt * 128 + n) * CC + s * 64 + cq * 8;
#pragma unroll
        for (int c = 0; c < 4; c++)
            cp_async16(dstRow + (((cq + c) ^ (n & 7)) << 4), src + c * 8);
        CP_COMMIT();
    };
    issueB(0);

    {
        const int rbase = wid * 8;
#pragma unroll
        for (int rr = 0; rr < 8; rr++) {
            const int r = rbase + rr;
            const float* xr = x + (size_t)(r0 + r) * CC;
            char* Arow = sm + r * 1024;
            const int xw = r & 7;
#pragma unroll
            for (int pass = 0; pass < 4; pass++) {
                const int k = pass * 128 + lane * 4;
                const float4 xv = *(const float4*)(xr + k);
                uint2 pk;
                ((__nv_bfloat162*)&pk)[0] = __floats2bfloat162_rn(xv.x, xv.y);
                ((__nv_bfloat162*)&pk)[1] = __floats2bfloat162_rn(xv.z, xv.w);
                const int c8 = pass * 16 + (lane >> 1);
                *(uint2*)(Arow + ((c8 ^ xw) << 4) + ((lane & 1) << 3)) = pk;
            }
        }
    }

    const int mw = wid & 1, nw = wid >> 1;
    const int mA  = mw * 32 + (lane & 15);
    const int aC8 = lane >> 4;
    const int aXr = mA & 7;
    const uint32_t aBase = smb + mA * 1024;
    const int nB  = nw * 32 + (lane & 7) + ((lane >> 4) << 3);
    const int bC8 = (lane >> 3) & 1;
    const int bXr = nB & 7;
    const uint32_t bRowOff = (uint32_t)nB * 128;

    float acc[2][4][4];
#pragma unroll
    for (int mf = 0; mf < 2; mf++)
#pragma unroll
        for (int nf = 0; nf < 4; nf++)
#pragma unroll
            for (int d = 0; d < 4; d++) acc[mf][nf][d] = 0.f;

#pragma unroll 1
    for (int s = 0; s < 8; s++) {
        CP_WAIT0();
        __syncthreads();
        if (s < 7) issueB(s + 1);
        const uint32_t Bslot = smb + EMB_OFF_B + (s & 1) * 16384;
#pragma unroll
        for (int t = 0; t < 4; t++) {
            uint32_t a0[4], a1[4], b0[4], b1[4];
            const uint32_t swA = (uint32_t)(((s * 8 + t * 2 + aC8) ^ aXr) << 4);
            ldsm4(a0, aBase + swA);
            ldsm4(a1, aBase + 16384 + swA);
            const uint32_t swB = (uint32_t)(((t * 2 + bC8) ^ bXr) << 4);
            const uint32_t bA = Bslot + bRowOff + swB;
            ldsm4(b0, bA);
            ldsm4(b1, bA + 2048);
            mma_bf16(acc[0][0], a0, b0);
            mma_bf16(acc[0][1], a0, b0 + 2);
            mma_bf16(acc[0][2], a0, b1);
            mma_bf16(acc[0][3], a0, b1 + 2);
            mma_bf16(acc[1][0], a1, b0);
            mma_bf16(acc[1][1], a1, b0 + 2);
            mma_bf16(acc[1][2], a1, b1);
            mma_bf16(acc[1][3], a1, b1 + 2);
        }
    }

    const int qrow = lane >> 2, qcol2 = (lane & 3) * 2;
    const int cbase = (nt & 3) * 128 + nw * 32;
    const float* bias = (nt < 4) ? bp : bx;
    float2 bb[4];
#pragma unroll
    for (int nf = 0; nf < 4; nf++)
        bb[nf] = *(const float2*)(bias + cbase + nf * 8 + qcol2);

    if (nt < 4) {
#pragma unroll
        for (int mf = 0; mf < 2; mf++)
#pragma unroll
            for (int h = 0; h < 2; h++) {
                const int row = r0 + mw * 32 + mf * 16 + h * 8 + qrow;
#pragma unroll
                for (int nf = 0; nf < 4; nf++) {
                    const int col = cbase + nf * 8 + qcol2;
                    *(float2*)(g_VE + (size_t)row * CC + col) =
                        make_float2(acc[mf][nf][h * 2] + bb[nf].x,
                                    acc[mf][nf][h * 2 + 1] + bb[nf].y);
                }
            }
    } else {
#pragma unroll
        for (int mf = 0; mf < 2; mf++)
#pragma unroll
            for (int h = 0; h < 2; h++) {
                const int row = r0 + mw * 32 + mf * 16 + h * 8 + qrow;
#pragma unroll
                for (int nf = 0; nf < 4; nf++) {
                    const int col = cbase + nf * 8 + qcol2;
                    *(__nv_bfloat162*)(g_XEh + (size_t)row * CC + col) =
                        __floats2bfloat162_rn(acc[mf][nf][h * 2] + bb[nf].x,
                                              acc[mf][nf][h * 2 + 1] + bb[nf].y);
                }
            }
    }
}

// ---------------------------------------------------------------------------
// Main kernel: PERSISTENT, 148 CTAs x 512 threads, 4 independent warpgroups.
// NEW: software-pipelined A-build. K in 8 stages of 64; per-group A is a
// 2 x 8 KB double buffer. Per stage: issue XE loads for s+1 (registers,
// in flight) -> MMA burst of stage s -> convert/store s+1 -> group barrier.
// XE gmem latency is hidden under the 64-HMMA burst.
// ---------------------------------------------------------------------------
__global__ __launch_bounds__(512, 1) void temporal_kernel(
    const float* __restrict__ x,
    const float* __restrict__ ts,
    const float* __restrict__ amask,
    const float* __restrict__ Wt,  const float* __restrict__ bt,
    const float* __restrict__ bim,
    float* __restrict__ out)
{
    extern __shared__ char sm[];
    const uint32_t smb = smem_u32(sm);
    const int tid   = threadIdx.x;
    const int lane  = tid & 31;
    const int g     = tid >> 7;          // warpgroup 0..3
    const int wg    = (tid >> 5) & 3;    // warp within group
    const int tid_g = tid & 127;

    const int chunk = blockIdx.x & 3;
    const int slot  = blockIdx.x >> 2;   // 0..36
    const int stream = slot * 4 + g;     // 0..147 within this chunk

    // ---- load resident B slice [128 n][512 k], XOR-swizzled ----
    {
        const __nv_bfloat16* Bsrc = g_WT + (size_t)(chunk * 128) * CC;
#pragma unroll 4
        for (int idx = tid; idx < 8192; idx += 512) {
            const int n = idx >> 6, c8 = idx & 63;
            cp_async16(smb + OFF_B + n * 1024 + ((c8 ^ (n & 7)) << 4),
                       Bsrc + (size_t)n * CC + c8 * 8);
        }
        CP_COMMIT();
    }

    float* sWt0 = (float*)(sm + OFF_WT0);
    float* sWt1 = (float*)(sm + OFF_WT1);
    float* sbt  = (float*)(sm + OFF_BT);
    float* sbim = (float*)(sm + OFF_BIM);
    char*  grp  = sm + OFF_GRP + g * 1536;
    float* f0s   = (float*)(grp + GRP_F0);
    float* f1s   = (float*)(grp + GRP_F1);
    float* maskv = (float*)(grp + GRP_MASK);
    float* sout2 = (float*)(grp + GRP_SOUT2);
    float* sexp  = (float*)(grp + GRP_SEXP);

    sWt0[tid] = Wt[tid];
    sWt1[tid] = Wt[CC + tid];
    sbt[tid]  = bt[tid];
    sbim[tid] = bim[tid];
    if (tid_g < 128) sexp[tid_g] = 0.f;
    if (tid_g < 64)  sout2[tid_g] = 0.f;

    CP_WAIT0();
    __syncthreads();   // B + staging visible; groups diverge after this

    // ---- geometry ----
    const int mw = wg & 1, nw = wg >> 1;
    const int m0  = mw * 32;
    const int n0w = nw * 64;
    const int mA  = m0 + (lane & 15);
    const int aC8 = lane >> 4;
    const int aXr = mA & 7;
    const int nB  = n0w + (lane & 7) + ((lane >> 4) << 3);
    const int bC8 = (lane >> 3) & 1;
    const int bXr = nB & 7;
    const uint32_t bBase = smb + OFF_B + (uint32_t)nB * 1024;
    const int qrow = lane >> 2, qcol2 = (lane & 3) * 2;

    // A-build thread mapping: ro = tid_g>>3 (0..15), c8b = tid_g&7 (k-octet)
    const int ro  = tid_g >> 3;
    const int c8b = tid_g & 7;
    char* Ag = sm + OFF_A + g * 16384;               // 2 slots x 8192 B

    float* gout2 = out + BB * TT * CC;
    const int ntiles = (stream < 136) ? 7 : 6;       // 1024 = 148*6 + 136

#pragma unroll 1
    for (int t = 0; t < ntiles; t++) {
        const int idx = stream + 148 * t;
        const int b = idx >> 6, i = idx & 63;
        const __nv_bfloat16* XEb = g_XEh + (size_t)(b * TT) * CC;

        // ---- per-tile staging ----
        if (tid_g < 64) {
            const float rel = ts[b * TT + i] - ts[b * TT + tid_g];
            f0s[tid_g] = log1pf(fmaxf(rel, 0.f));
            f1s[tid_g] = log1pf(fmaxf(-rel, 0.f));
            maskv[tid_g] = amask[b * TT + tid_g];
        }
        bar_grp(g + 1);

        // ---- build stage 0 into slot 0 ----
        {
            const int kb = c8b * 8;
            const float4 w0a = *(const float4*)(sWt0 + kb);
            const float4 w0b = *(const float4*)(sWt0 + kb + 4);
            const float4 w1a = *(const float4*)(sWt1 + kb);
            const float4 w1b = *(const float4*)(sWt1 + kb + 4);
            const float4 bta = *(const float4*)(sbt + kb);
            const float4 btb = *(const float4*)(sbt + kb + 4);
#pragma unroll
            for (int it = 0; it < 4; it++) {
                const int r = ro + it * 16;
                const float f0v = f0s[r], f1v = f1s[r];
                const uint4 xp = *(const uint4*)(XEb + (size_t)r * CC + kb);
                const __nv_bfloat162* x2 = (const __nv_bfloat162*)&xp;
                uint4 pk; __nv_bfloat162* p2 = (__nv_bfloat162*)&pk;
                float2 xe;
                xe = __bfloat1622float2(x2[0]);
                p2[0] = __floats2bfloat162_rn(
                    fmaxf(fmaf(f0v, w0a.x, fmaf(f1v, w1a.x, bta.x)) + xe.x, 0.f),
                    fmaxf(fmaf(f0v, w0a.y, fmaf(f1v, w1a.y, bta.y)) + xe.y, 0.f));
                xe = __bfloat1622float2(x2[1]);
                p2[1] = __floats2bfloat162_rn(
                    fmaxf(fmaf(f0v, w0a.z, fmaf(f1v, w1a.z, bta.z)) + xe.x, 0.f),
                    fmaxf(fmaf(f0v, w0a.w, fmaf(f1v, w1a.w, bta.w)) + xe.y, 0.f));
                xe = __bfloat1622float2(x2[2]);
                p2[2] = __floats2bfloat162_rn(
                    fmaxf(fmaf(f0v, w0b.x, fmaf(f1v, w1b.x, btb.x)) + xe.x, 0.f),
                    fmaxf(fmaf(f0v, w0b.y, fmaf(f1v, w1b.y, btb.y)) + xe.y, 0.f));
                xe = __bfloat1622float2(x2[3]);
                p2[3] = __floats2bfloat162_rn(
                    fmaxf(fmaf(f0v, w0b.z, fmaf(f1v, w1b.z, btb.z)) + xe.x, 0.f),
                    fmaxf(fmaf(f0v, w0b.w, fmaf(f1v, w1b.w, btb.w)) + xe.y, 0.f));
                *(uint4*)(Ag + r * 128 + ((c8b ^ (r & 7)) << 4)) = pk;
            }
        }
        bar_grp(g + 1);

        float acc[2][8][4];
#pragma unroll
        for (int mf = 0; mf < 2; mf++)
#pragma unroll
            for (int nf = 0; nf < 8; nf++)
#pragma unroll
                for (int d = 0; d < 4; d++) acc[mf][nf][d] = 0.f;

        // ---- pipelined stages ----
#pragma unroll 1
        for (int s = 0; s < 8; s++) {
            const uint32_t aBase = smb + OFF_A + g * 16384 + (s & 1) * 8192
                                   + (uint32_t)mA * 128;

            // 1) issue XE loads for stage s+1 (in flight during MMA)
            uint4 xp[4];
            if (s < 7) {
                const int kb = (s + 1) * 64 + c8b * 8;
#pragma unroll
                for (int it = 0; it < 4; it++)
                    xp[it] = *(const uint4*)(XEb + (size_t)(ro + it * 16) * CC + kb);
            }

            // 2) MMA burst for stage s
#pragma unroll
            for (int tk = 0; tk < 4; tk++) {
                uint32_t a0[4], a1[4], bf[4][4];
                const uint32_t swA = (uint32_t)(((tk * 2 + aC8) ^ aXr) << 4);
                ldsm4(a0, aBase + swA);
                ldsm4(a1, aBase + 2048 + swA);       // +16 rows * 128 B
                const uint32_t cB = (uint32_t)(s * 8 + tk * 2 + bC8);
                const uint32_t swB = ((cB ^ (uint32_t)bXr) << 4);
                ldsm4(bf[0], bBase + swB);
                ldsm4(bf[1], bBase + 16384 + swB);
                ldsm4(bf[2], bBase + 32768 + swB);
                ldsm4(bf[3], bBase + 49152 + swB);
#pragma unroll
                for (int qq = 0; qq < 4; qq++) {
                    mma_bf16(acc[0][qq * 2],     a0, bf[qq]);
                    mma_bf16(acc[0][qq * 2 + 1], a0, bf[qq] + 2);
                    mma_bf16(acc[1][qq * 2],     a1, bf[qq]);
                    mma_bf16(acc[1][qq * 2 + 1], a1, bf[qq] + 2);
                }
            }

            // 3) convert + store stage s+1 into the alternate slot
            if (s < 7) {
                const int kb = (s + 1) * 64 + c8b * 8;
                const float4 w0a = *(const float4*)(sWt0 + kb);
                const float4 w0b = *(const float4*)(sWt0 + kb + 4);
                const float4 w1a = *(const float4*)(sWt1 + kb);
                const float4 w1b = *(const float4*)(sWt1 + kb + 4);
                const float4 bta = *(const float4*)(sbt + kb);
                const float4 btb = *(const float4*)(sbt + kb + 4);
                char* Adst = Ag + ((s + 1) & 1) * 8192;
#pragma unroll
                for (int it = 0; it < 4; it++) {
                    const int r = ro + it * 16;
                    const float f0v = f0s[r], f1v = f1s[r];
                    const __nv_bfloat162* x2 = (const __nv_bfloat162*)&xp[it];
                    uint4 pk; __nv_bfloat162* p2 = (__nv_bfloat162*)&pk;
                    float2 xe;
                    xe = __bfloat1622float2(x2[0]);
                    p2[0] = __floats2bfloat162_rn(
                        fmaxf(fmaf(f0v, w0a.x, fmaf(f1v, w1a.x, bta.x)) + xe.x, 0.f),
                        fmaxf(fmaf(f0v, w0a.y, fmaf(f1v, w1a.y, bta.y)) + xe.y, 0.f));
                    xe = __bfloat1622float2(x2[1]);
                    p2[1] = __floats2bfloat162_rn(
                        fmaxf(fmaf(f0v, w0a.z, fmaf(f1v, w1a.z, bta.z)) + xe.x, 0.f),
                        fmaxf(fmaf(f0v, w0a.w, fmaf(f1v, w1a.w, bta.w)) + xe.y, 0.f));
                    xe = __bfloat1622float2(x2[2]);
                    p2[2] = __floats2bfloat162_rn(
                        fmaxf(fmaf(f0v, w0b.x, fmaf(f1v, w1b.x, btb.x)) + xe.x, 0.f),
                        fmaxf(fmaf(f0v, w0b.y, fmaf(f1v, w1b.y, btb.y)) + xe.y, 0.f));
                    xe = __bfloat1622float2(x2[3]);
                    p2[3] = __floats2bfloat162_rn(
                        fmaxf(fmaf(f0v, w0b.z, fmaf(f1v, w1b.z, btb.z)) + xe.x, 0.f),
                        fmaxf(fmaf(f0v, w0b.w, fmaf(f1v, w1b.w, btb.w)) + xe.y, 0.f));
                    *(uint4*)(Adst + r * 128 + ((c8b ^ (r & 7)) << 4)) = pk;
                }
            }
            bar_grp(g + 1);
        }

        // ---- register epilogue (two n-halves), group-local reductions ----
        float rs[4] = {0.f, 0.f, 0.f, 0.f};
#pragma unroll
        for (int nh = 0; nh < 2; nh++) {
            float bimv[8], cs[8];
#pragma unroll
            for (int nf = 0; nf < 4; nf++) {
                bimv[nf * 2]     = sbim[chunk * 128 + n0w + nh * 32 + nf * 8 + qcol2];
                bimv[nf * 2 + 1] = sbim[chunk * 128 + n0w + nh * 32 + nf * 8 + qcol2 + 1];
                cs[nf * 2] = 0.f; cs[nf * 2 + 1] = 0.f;
            }
#pragma unroll
            for (int mf = 0; mf < 2; mf++) {
#pragma unroll
                for (int h = 0; h < 2; h++) {
                    const int r  = m0 + mf * 16 + h * 8 + qrow;
                    const float hmk = 0.5f * maskv[r];
                    const float* VEr = g_VE + (size_t)(b * TT + r) * CC
                                       + chunk * 128 + n0w + nh * 32 + qcol2;
                    float rsum = 0.f;
#pragma unroll
                    for (int nf = 0; nf < 4; nf++) {
                        const float2 ve = *(const float2*)(VEr + nf * 8);
                        const float s0 = acc[mf][nh * 4 + nf][h * 2 + 0] + bimv[nf * 2];
                        const float s1 = acc[mf][nh * 4 + nf][h * 2 + 1] + bimv[nf * 2 + 1];
                        const float p0 = fmaf(tanh_fast(0.5f * s0), hmk, hmk);
                        const float p1 = fmaf(tanh_fast(0.5f * s1), hmk, hmk);
                        rsum += p0 + p1;
                        cs[nf * 2]     += __expf(ve.x * p0);
                        cs[nf * 2 + 1] += __expf(ve.y * p1);
                    }
                    rs[mf * 2 + h] += rsum;
                }
            }
#pragma unroll
            for (int c = 0; c < 8; c++) {
                cs[c] += __shfl_xor_sync(0xffffffffu, cs[c], 4);
                cs[c] += __shfl_xor_sync(0xffffffffu, cs[c], 8);
                cs[c] += __shfl_xor_sync(0xffffffffu, cs[c], 16);
            }
            if (lane < 4) {
#pragma unroll
                for (int nf = 0; nf < 4; nf++) {
                    atomicAdd(&sexp[n0w + nh * 32 + nf * 8 + lane * 2],     cs[nf * 2]);
                    atomicAdd(&sexp[n0w + nh * 32 + nf * 8 + lane * 2 + 1], cs[nf * 2 + 1]);
                }
            }
        }
#pragma unroll
        for (int q = 0; q < 4; q++) {
            rs[q] += __shfl_xor_sync(0xffffffffu, rs[q], 1);
            rs[q] += __shfl_xor_sync(0xffffffffu, rs[q], 2);
        }
        if ((lane & 3) == 0) {
#pragma unroll
            for (int q = 0; q < 4; q++)
                atomicAdd(&sout2[m0 + (q >> 1) * 16 + (q & 1) * 8 + qrow], rs[q]);
        }
        bar_grp(g + 1);

        // ---- outputs ----
        if (tid_g < 128) {
            const int ng = chunk * 128 + tid_g;
            const int row = b * TT + i;
            out[(size_t)row * CC + ng] = x[(size_t)row * CC + ng] + __logf(sexp[tid_g]);
            sexp[tid_g] = 0.f;
        }
        if (tid_g < 64) {
            atomicAdd(&gout2[(b * TT + i) * TT + tid_g], sout2[tid_g] * (1.f / 512.f));
            sout2[tid_g] = 0.f;
        }
        bar_grp(g + 1);
    }
}

// ---------------------------------------------------------------------------
extern "C" void kernel_launch(void* const* d_in, const int* in_sizes, int n_in,
                              void* d_out, int out_size)
{
    const float* x     = (const float*)d_in[0];
    const float* ts    = (const float*)d_in[1];
    const float* amask = (const float*)d_in[2];
    const float* Wp    = (const float*)d_in[3];
    const float* bp    = (const float*)d_in[4];
    const float* Wx    = (const float*)d_in[5];
    const float* bx    = (const float*)d_in[6];
    const float* Wt    = (const float*)d_in[7];
    const float* bt    = (const float*)d_in[8];
    const float* Wim   = (const float*)d_in[9];
    const float* bim   = (const float*)d_in[10];
    float* out = (float*)d_out;

    zero_out2_kernel<<<256, 256>>>(out);
    prep_w_kernel<<<dim3(16, 16, 3), dim3(32, 32)>>>(Wim, Wp, Wx);

    cudaFuncSetAttribute(embed_mma_kernel, cudaFuncAttributeMaxDynamicSharedMemorySize, EMB_SMEM);
    embed_mma_kernel<<<128, 256, EMB_SMEM>>>(x, bp, bx);

    cudaFuncSetAttribute(temporal_kernel, cudaFuncAttributeMaxDynamicSharedMemorySize, SMEM_BYTES);
    temporal_kernel<<<148, 512, SMEM_BYTES>>>(x, ts, amask, Wt, bt, bim, out);
}